// round 1
// baseline (speedup 1.0000x reference)
#include <cuda_runtime.h>
#include <math.h>

// ---------------------------------------------------------------------------
// MultiheadAttention: B=1, L=S=4096, E=1024, H=16, D=64
//   q = query @ wq^T + bq ; k,v likewise
//   scores = (q_h @ k_h^T) / sqrt(D)    [H, L, S]
//   attn = softmax(scores) (optional causal mask)
//   o_h = attn_h @ v_h ; out = o @ fc^T + fc_b
// Outputs: out [L,E] and attn_weights [H,L,S] (if out_size covers both).
// ---------------------------------------------------------------------------

#define E_DIM 1024
#define H_HEADS 16
#define D_HEAD 64
#define L_MAX 4096

// Static device scratch (allocation-free kernel_launch).
__device__ float g_q[L_MAX * E_DIM];
__device__ float g_k[L_MAX * E_DIM];
__device__ float g_v[L_MAX * E_DIM];
__device__ float g_o[L_MAX * E_DIM];
// Fallback attn buffer in case d_out only holds `out`.
__device__ float g_attn[(size_t)H_HEADS * L_MAX * L_MAX];

// ---------------------------------------------------------------------------
// Generic NT GEMM with bias: C[m][n] = sum_k A[m*K+k] * B[n*K+k] + bias[n]
// 64x64 tile, BK=16, 256 threads, 4x4 micro-tile.
// Requires M%64==0, N%64==0, K%16==0 and 16B-aligned rows (K%4==0).
// ---------------------------------------------------------------------------
__global__ __launch_bounds__(256)
void gemm_nt_bias(const float* __restrict__ A, const float* __restrict__ B,
                  const float* __restrict__ bias, float* __restrict__ C,
                  int M, int N, int K)
{
    __shared__ float As[16][68];   // As[k][m]
    __shared__ float Bs[16][68];   // Bs[k][n]

    const int tid = threadIdx.x;
    const int tx = tid & 15;
    const int ty = tid >> 4;
    const int m0 = blockIdx.y * 64;
    const int n0 = blockIdx.x * 64;

    float acc[4][4];
#pragma unroll
    for (int i = 0; i < 4; i++)
#pragma unroll
        for (int j = 0; j < 4; j++) acc[i][j] = 0.f;

    const int lrow = tid >> 2;          // 0..63
    const int lcol = (tid & 3) * 4;     // 0,4,8,12

    for (int k0 = 0; k0 < K; k0 += 16) {
        float4 a = *(const float4*)(A + (size_t)(m0 + lrow) * K + k0 + lcol);
        float4 b = *(const float4*)(B + (size_t)(n0 + lrow) * K + k0 + lcol);
        As[lcol + 0][lrow] = a.x; As[lcol + 1][lrow] = a.y;
        As[lcol + 2][lrow] = a.z; As[lcol + 3][lrow] = a.w;
        Bs[lcol + 0][lrow] = b.x; Bs[lcol + 1][lrow] = b.y;
        Bs[lcol + 2][lrow] = b.z; Bs[lcol + 3][lrow] = b.w;
        __syncthreads();

#pragma unroll
        for (int kk = 0; kk < 16; kk++) {
            float av[4], bv[4];
#pragma unroll
            for (int i = 0; i < 4; i++) av[i] = As[kk][ty * 4 + i];
#pragma unroll
            for (int j = 0; j < 4; j++) bv[j] = Bs[kk][tx * 4 + j];
#pragma unroll
            for (int i = 0; i < 4; i++)
#pragma unroll
                for (int j = 0; j < 4; j++) acc[i][j] += av[i] * bv[j];
        }
        __syncthreads();
    }

#pragma unroll
    for (int i = 0; i < 4; i++) {
        const int m = m0 + ty * 4 + i;
#pragma unroll
        for (int j = 0; j < 4; j++) {
            const int n = n0 + tx * 4 + j;
            C[(size_t)m * N + n] = acc[i][j] + bias[n];
        }
    }
}

// ---------------------------------------------------------------------------
// scores[h][l][s] = (1/8) * sum_d Q[l][h*64+d] * K[s][h*64+d]
// One 64x64 output tile per block; full K=64 depth in one smem load.
// grid: (S/64, L/64, H)
// ---------------------------------------------------------------------------
__global__ __launch_bounds__(256)
void scores_kernel(const float* __restrict__ Q, const float* __restrict__ Kv,
                   float* __restrict__ attn, int L, int S, float inv_scale)
{
    __shared__ float Qs[64][68];   // Qs[d][m]
    __shared__ float Ks[64][68];   // Ks[d][n]

    const int tid = threadIdx.x;
    const int tx = tid & 15;
    const int ty = tid >> 4;
    const int n0 = blockIdx.x * 64;
    const int m0 = blockIdx.y * 64;
    const int h  = blockIdx.z;
    const int hoff = h * D_HEAD;

#pragma unroll
    for (int i = 0; i < 4; i++) {
        const int lin = tid + i * 256;          // 0..1023
        const int m = lin >> 4;                 // 0..63
        const int d4 = (lin & 15) * 4;          // 0..60
        float4 q = *(const float4*)(Q + (size_t)(m0 + m) * E_DIM + hoff + d4);
        float4 k = *(const float4*)(Kv + (size_t)(n0 + m) * E_DIM + hoff + d4);
        Qs[d4 + 0][m] = q.x; Qs[d4 + 1][m] = q.y; Qs[d4 + 2][m] = q.z; Qs[d4 + 3][m] = q.w;
        Ks[d4 + 0][m] = k.x; Ks[d4 + 1][m] = k.y; Ks[d4 + 2][m] = k.z; Ks[d4 + 3][m] = k.w;
    }
    __syncthreads();

    float acc[4][4];
#pragma unroll
    for (int i = 0; i < 4; i++)
#pragma unroll
        for (int j = 0; j < 4; j++) acc[i][j] = 0.f;

#pragma unroll 8
    for (int kk = 0; kk < 64; kk++) {
        float av[4], bv[4];
#pragma unroll
        for (int i = 0; i < 4; i++) av[i] = Qs[kk][ty * 4 + i];
#pragma unroll
        for (int j = 0; j < 4; j++) bv[j] = Ks[kk][tx * 4 + j];
#pragma unroll
        for (int i = 0; i < 4; i++)
#pragma unroll
            for (int j = 0; j < 4; j++) acc[i][j] += av[i] * bv[j];
    }

    float* base = attn + (size_t)h * L * S;
#pragma unroll
    for (int i = 0; i < 4; i++) {
        const int m = m0 + ty * 4 + i;
#pragma unroll
        for (int j = 0; j < 4; j++) {
            const int n = n0 + tx * 4 + j;
            base[(size_t)m * S + n] = acc[i][j] * inv_scale;
        }
    }
}

// ---------------------------------------------------------------------------
// Row softmax over attn[h][l][:], in place, optional causal mask (s <= l valid).
// One block per (h,l) row. 256 threads, 16 elements/thread (S=4096).
// ---------------------------------------------------------------------------
__global__ __launch_bounds__(256)
void softmax_kernel(float* __restrict__ attn, int L, int S,
                    const int* __restrict__ causal_flag)
{
    const int row = blockIdx.x;          // 0 .. H*L-1
    const int l = row % L;
    const bool causal = (*causal_flag) != 0;
    float* p = attn + (size_t)row * S;

    const int tid = threadIdx.x;
    const int per = S / (256 * 4);       // float4s per thread (=4 for S=4096)

    float v[16];
    float m = -INFINITY;
    for (int i = 0; i < per; i++) {
        const int idx4 = tid + i * 256;
        float4 x = *(const float4*)(p + idx4 * 4);
        const int s0 = idx4 * 4;
        float* vv = v + i * 4;
        vv[0] = x.x; vv[1] = x.y; vv[2] = x.z; vv[3] = x.w;
#pragma unroll
        for (int j = 0; j < 4; j++) {
            const bool ok = !causal || (s0 + j <= l);
            if (ok) m = fmaxf(m, vv[j]);
            else vv[j] = -INFINITY;   // mark masked
        }
    }

    __shared__ float red[32];
    // warp reduce max
#pragma unroll
    for (int o = 16; o > 0; o >>= 1) m = fmaxf(m, __shfl_xor_sync(0xffffffffu, m, o));
    if ((tid & 31) == 0) red[tid >> 5] = m;
    __syncthreads();
    if (tid < 32) {
        float t = (tid < 8) ? red[tid] : -INFINITY;
#pragma unroll
        for (int o = 4; o > 0; o >>= 1) t = fmaxf(t, __shfl_xor_sync(0xffffffffu, t, o));
        red[tid] = t;
    }
    __syncthreads();
    m = red[0];

    float sum = 0.f;
    for (int i = 0; i < per * 4; i++) {
        float e = (v[i] == -INFINITY) ? 0.f : __expf(v[i] - m);
        v[i] = e;
        sum += e;
    }
    __syncthreads();
#pragma unroll
    for (int o = 16; o > 0; o >>= 1) sum += __shfl_xor_sync(0xffffffffu, sum, o);
    if ((tid & 31) == 0) red[tid >> 5] = sum;
    __syncthreads();
    if (tid < 32) {
        float t = (tid < 8) ? red[tid] : 0.f;
#pragma unroll
        for (int o = 4; o > 0; o >>= 1) t += __shfl_xor_sync(0xffffffffu, t, o);
        red[tid] = t;
    }
    __syncthreads();
    const float inv = 1.0f / red[0];

    for (int i = 0; i < per; i++) {
        const int idx4 = tid + i * 256;
        float* vv = v + i * 4;
        float4 x = make_float4(vv[0] * inv, vv[1] * inv, vv[2] * inv, vv[3] * inv);
        *(float4*)(p + idx4 * 4) = x;
    }
}

// ---------------------------------------------------------------------------
// O[l][h*64+d] = sum_s P[h][l][s] * V[s][h*64+d]
// BM=64, BN=64(=D), BK=16. grid: (L/64, H)
// ---------------------------------------------------------------------------
__global__ __launch_bounds__(256)
void pv_kernel(const float* __restrict__ attn, const float* __restrict__ V,
               float* __restrict__ O, int L, int S)
{
    __shared__ float Ps[16][68];   // Ps[k][m]
    __shared__ float Vs[16][68];   // Vs[k][d]

    const int tid = threadIdx.x;
    const int tx = tid & 15;
    const int ty = tid >> 4;
    const int m0 = blockIdx.x * 64;
    const int h  = blockIdx.y;
    const int hoff = h * D_HEAD;
    const float* P = attn + (size_t)h * L * S;

    float acc[4][4];
#pragma unroll
    for (int i = 0; i < 4; i++)
#pragma unroll
        for (int j = 0; j < 4; j++) acc[i][j] = 0.f;

    const int prow = tid >> 2;           // 0..63
    const int pcol = (tid & 3) * 4;      // 0..12
    const int vkk = tid >> 4;            // 0..15
    const int vd4 = (tid & 15) * 4;      // 0..60

    for (int k0 = 0; k0 < S; k0 += 16) {
        float4 a = *(const float4*)(P + (size_t)(m0 + prow) * S + k0 + pcol);
        Ps[pcol + 0][prow] = a.x; Ps[pcol + 1][prow] = a.y;
        Ps[pcol + 2][prow] = a.z; Ps[pcol + 3][prow] = a.w;
        float4 b = *(const float4*)(V + (size_t)(k0 + vkk) * E_DIM + hoff + vd4);
        Vs[vkk][vd4 + 0] = b.x; Vs[vkk][vd4 + 1] = b.y;
        Vs[vkk][vd4 + 2] = b.z; Vs[vkk][vd4 + 3] = b.w;
        __syncthreads();

#pragma unroll
        for (int kk = 0; kk < 16; kk++) {
            float av[4], bv[4];
#pragma unroll
            for (int i = 0; i < 4; i++) av[i] = Ps[kk][ty * 4 + i];
#pragma unroll
            for (int j = 0; j < 4; j++) bv[j] = Vs[kk][tx * 4 + j];
#pragma unroll
            for (int i = 0; i < 4; i++)
#pragma unroll
                for (int j = 0; j < 4; j++) acc[i][j] += av[i] * bv[j];
        }
        __syncthreads();
    }

#pragma unroll
    for (int i = 0; i < 4; i++) {
        const int m = m0 + ty * 4 + i;
#pragma unroll
        for (int j = 0; j < 4; j++) {
            O[(size_t)m * E_DIM + hoff + tx * 4 + j] = acc[i][j];
        }
    }
}

// ---------------------------------------------------------------------------
// Launch
// ---------------------------------------------------------------------------
extern "C" void kernel_launch(void* const* d_in, const int* in_sizes, int n_in,
                              void* d_out, int out_size)
{
    const float* query = (const float*)d_in[0];
    const float* key   = (const float*)d_in[1];
    const float* value = (const float*)d_in[2];
    const float* wq_w  = (const float*)d_in[3];
    const float* wq_b  = (const float*)d_in[4];
    const float* wk_w  = (const float*)d_in[5];
    const float* wk_b  = (const float*)d_in[6];
    const float* wv_w  = (const float*)d_in[7];
    const float* wv_b  = (const float*)d_in[8];
    const float* fc_w  = (const float*)d_in[9];
    const float* fc_b  = (const float*)d_in[10];
    const int* causal  = (const int*)d_in[11];

    const int L = in_sizes[0] / E_DIM;   // B=1
    const int S = in_sizes[1] / E_DIM;

    float* out = (float*)d_out;

    // attn goes into d_out if the harness scores both outputs, else scratch.
    float* attn_ptr;
    {
        size_t need = (size_t)L * E_DIM + (size_t)H_HEADS * L * S;
        if ((size_t)out_size >= need) {
            attn_ptr = out + (size_t)L * E_DIM;
        } else {
            cudaGetSymbolAddress((void**)&attn_ptr, g_attn);
        }
    }

    float *qb, *kb, *vb, *ob;
    cudaGetSymbolAddress((void**)&qb, g_q);
    cudaGetSymbolAddress((void**)&kb, g_k);
    cudaGetSymbolAddress((void**)&vb, g_v);
    cudaGetSymbolAddress((void**)&ob, g_o);

    dim3 blk(256);

    // Projections: X @ W^T + b
    {
        dim3 grid(E_DIM / 64, L / 64);
        gemm_nt_bias<<<grid, blk>>>(query, wq_w, wq_b, qb, L, E_DIM, E_DIM);
        gemm_nt_bias<<<grid, blk>>>(key,   wk_w, wk_b, kb, S, E_DIM, E_DIM);
        gemm_nt_bias<<<grid, blk>>>(value, wv_w, wv_b, vb, S, E_DIM, E_DIM);
    }

    // Scores (scaled) -> attn
    {
        dim3 grid(S / 64, L / 64, H_HEADS);
        scores_kernel<<<grid, blk>>>(qb, kb, attn_ptr, L, S, 0.125f);
    }

    // Softmax in place
    {
        dim3 grid(H_HEADS * L);
        softmax_kernel<<<grid, blk>>>(attn_ptr, L, S, causal);
    }

    // attn @ V -> O
    {
        dim3 grid(L / 64, H_HEADS);
        pv_kernel<<<grid, blk>>>(attn_ptr, vb, ob, L, S);
    }

    // FC: O @ fc_w^T + fc_b -> out
    {
        dim3 grid(E_DIM / 64, L / 64);
        gemm_nt_bias<<<grid, blk>>>(ob, fc_w, fc_b, out, L, E_DIM, E_DIM);
    }
}

// round 3
// speedup vs baseline: 1.8109x; 1.8109x over previous
#include <cuda_runtime.h>
#include <cuda_bf16.h>
#include <stdint.h>
#include <math.h>

#define E_DIM 1024
#define H_HEADS 16
#define D_HEAD 64
#define L_MAX 4096

// ---------------------------------------------------------------------------
// Device scratch (allocation-free kernel_launch)
// ---------------------------------------------------------------------------
__device__ __nv_bfloat16 g_xq_h[L_MAX * E_DIM], g_xq_l[L_MAX * E_DIM];
__device__ __nv_bfloat16 g_xk_h[L_MAX * E_DIM], g_xk_l[L_MAX * E_DIM];
__device__ __nv_bfloat16 g_xv_h[L_MAX * E_DIM], g_xv_l[L_MAX * E_DIM];
__device__ __nv_bfloat16 g_wq_h[E_DIM * E_DIM], g_wq_l[E_DIM * E_DIM];
__device__ __nv_bfloat16 g_wk_h[E_DIM * E_DIM], g_wk_l[E_DIM * E_DIM];
__device__ __nv_bfloat16 g_wv_h[E_DIM * E_DIM], g_wv_l[E_DIM * E_DIM];
__device__ __nv_bfloat16 g_fc_h[E_DIM * E_DIM], g_fc_l[E_DIM * E_DIM];
__device__ __nv_bfloat16 g_q_h[L_MAX * E_DIM], g_q_l[L_MAX * E_DIM];
__device__ __nv_bfloat16 g_k_h[L_MAX * E_DIM], g_k_l[L_MAX * E_DIM];
__device__ __nv_bfloat16 g_vt_h[E_DIM * L_MAX], g_vt_l[E_DIM * L_MAX];   // [E][S]
__device__ __nv_bfloat16 g_o_h[L_MAX * E_DIM], g_o_l[L_MAX * E_DIM];
__device__ float g_attn_fb[(size_t)H_HEADS * L_MAX * L_MAX];

#define DINLINE __device__ __forceinline__

DINLINE uint32_t smem_u32(const void* p) {
    uint32_t a;
    asm("{ .reg .u64 t; cvta.to.shared.u64 t, %1; cvt.u32.u64 %0, t; }" : "=r"(a) : "l"(p));
    return a;
}
DINLINE uint32_t sw128(uint32_t off) { return off ^ ((off >> 3) & 0x70); }

DINLINE void ldsm_x4(uint32_t& r0, uint32_t& r1, uint32_t& r2, uint32_t& r3, uint32_t addr) {
    asm volatile("ldmatrix.sync.aligned.m8n8.x4.shared.b16 {%0,%1,%2,%3}, [%4];"
                 : "=r"(r0), "=r"(r1), "=r"(r2), "=r"(r3) : "r"(addr));
}
DINLINE void ldsm_x2(uint32_t& r0, uint32_t& r1, uint32_t addr) {
    asm volatile("ldmatrix.sync.aligned.m8n8.x2.shared.b16 {%0,%1}, [%2];"
                 : "=r"(r0), "=r"(r1) : "r"(addr));
}
DINLINE void mma16816(float c[4], uint32_t a0, uint32_t a1, uint32_t a2, uint32_t a3,
                      uint32_t b0, uint32_t b1) {
    asm volatile(
        "mma.sync.aligned.m16n8k16.row.col.f32.bf16.bf16.f32 "
        "{%0,%1,%2,%3}, {%4,%5,%6,%7}, {%8,%9}, {%0,%1,%2,%3};"
        : "+f"(c[0]), "+f"(c[1]), "+f"(c[2]), "+f"(c[3])
        : "r"(a0), "r"(a1), "r"(a2), "r"(a3), "r"(b0), "r"(b1));
}

DINLINE uint32_t bf2u(__nv_bfloat16 a, __nv_bfloat16 b) {
    __nv_bfloat162 t = __halves2bfloat162(a, b);
    return *reinterpret_cast<uint32_t*>(&t);
}
DINLINE uint32_t packf_hi(float a, float b) {
    return bf2u(__float2bfloat16(a), __float2bfloat16(b));
}

// ---------------------------------------------------------------------------
// Core: one KC=64 chunk, bf16x3 emulated-fp32. Tiles in smem, 128B rows, SW128.
// A rows: warpM..warpM+MT*16, B rows (n-major): warpN..warpN+NT*8.
// ---------------------------------------------------------------------------
template<int MT, int NT>
DINLINE void compute_chunk(uint32_t aHi, uint32_t aLo, uint32_t bHi, uint32_t bLo,
                           int warpM, int warpN, int lane, float (&acc)[MT][NT][4])
{
    const int arow = lane & 15, asel = lane >> 4;
    const int brow = lane & 7,  bsel = (lane >> 3) & 1;
#pragma unroll
    for (int ks = 0; ks < 4; ks++) {
        uint32_t bfh[NT][2], bfl[NT][2];
        const uint32_t bcol = (uint32_t)(ks * 16 + bsel * 8) * 2;
#pragma unroll
        for (int nt = 0; nt < NT; nt++) {
            uint32_t off = sw128((uint32_t)(warpN + nt * 8 + brow) * 128 + bcol);
            ldsm_x2(bfh[nt][0], bfh[nt][1], bHi + off);
            ldsm_x2(bfl[nt][0], bfl[nt][1], bLo + off);
        }
        const uint32_t acol = (uint32_t)(ks * 16 + asel * 8) * 2;
#pragma unroll
        for (int mt = 0; mt < MT; mt++) {
            uint32_t off = sw128((uint32_t)(warpM + mt * 16 + arow) * 128 + acol);
            uint32_t a0, a1, a2, a3, l0, l1, l2, l3;
            ldsm_x4(a0, a1, a2, a3, aHi + off);
            ldsm_x4(l0, l1, l2, l3, aLo + off);
#pragma unroll
            for (int nt = 0; nt < NT; nt++) {
                mma16816(acc[mt][nt], a0, a1, a2, a3, bfh[nt][0], bfh[nt][1]);
                mma16816(acc[mt][nt], a0, a1, a2, a3, bfl[nt][0], bfl[nt][1]);
                mma16816(acc[mt][nt], l0, l1, l2, l3, bfh[nt][0], bfh[nt][1]);
            }
        }
    }
}

// ---------------------------------------------------------------------------
// fp32 -> bf16 hi/lo split
// ---------------------------------------------------------------------------
__global__ void cvt_hilo(const float* __restrict__ x, __nv_bfloat16* __restrict__ h,
                         __nv_bfloat16* __restrict__ l, int n4)
{
    int i = blockIdx.x * blockDim.x + threadIdx.x;
    for (; i < n4; i += gridDim.x * blockDim.x) {
        float4 v = ((const float4*)x)[i];
        __nv_bfloat16 hx = __float2bfloat16(v.x), hy = __float2bfloat16(v.y);
        __nv_bfloat16 hz = __float2bfloat16(v.z), hw = __float2bfloat16(v.w);
        ((uint2*)h)[i] = make_uint2(bf2u(hx, hy), bf2u(hz, hw));
        ((uint2*)l)[i] = make_uint2(
            packf_hi(v.x - __bfloat162float(hx), v.y - __bfloat162float(hy)),
            packf_hi(v.z - __bfloat162float(hz), v.w - __bfloat162float(hw)));
    }
}

// ---------------------------------------------------------------------------
// GEMM (projections + FC): C[m][n] = sum_k A[m][k]*B[n][k] + bias[n]
// Block tile 128x128, KC=64, 8 warps (warp tile 64x32).
// mode 0: C hi/lo bf16 at [m][n]; mode 1: transposed hi/lo at [n][vt_stride]+m;
// mode 2: fp32 at [m][n].
// ---------------------------------------------------------------------------
__global__ __launch_bounds__(256)
void gemm_hmma(const __nv_bfloat16* __restrict__ Ah, const __nv_bfloat16* __restrict__ Al,
               const __nv_bfloat16* __restrict__ Bh, const __nv_bfloat16* __restrict__ Bl,
               const float* __restrict__ bias,
               __nv_bfloat16* __restrict__ Ch, __nv_bfloat16* __restrict__ Cl,
               float* __restrict__ Cf,
               int mode, int N, int K, int vt_stride)
{
    extern __shared__ char smem[];
    const uint32_t sb = smem_u32(smem);
    const uint32_t tb = (sb + 1023) & ~1023u;
    char* tile = smem + (tb - sb);
    const uint32_t AH = 0, AL = 16384, BH = 32768, BL = 49152;

    const int tid = threadIdx.x, wid = tid >> 5, lane = tid & 31;
    const int m0 = blockIdx.y * 128, n0 = blockIdx.x * 128;
    const int warpM = (wid >> 2) * 64, warpN = (wid & 3) * 32;

    float acc[4][4][4];
#pragma unroll
    for (int a = 0; a < 4; a++)
#pragma unroll
        for (int b = 0; b < 4; b++)
#pragma unroll
            for (int c = 0; c < 4; c++) acc[a][b][c] = 0.f;

    const int lrow = tid >> 1, qb = (tid & 1) * 4;
    for (int c = 0; c < (K >> 6); c++) {
        const size_t aoff = (size_t)(m0 + lrow) * K + c * 64;
        const size_t boff = (size_t)(n0 + lrow) * K + c * 64;
#pragma unroll
        for (int j = 0; j < 4; j++) {
            const int q = qb + j;
            const uint32_t so = sw128((uint32_t)lrow * 128 + q * 16);
            *(uint4*)(tile + AH + so) = *(const uint4*)(Ah + aoff + q * 8);
            *(uint4*)(tile + AL + so) = *(const uint4*)(Al + aoff + q * 8);
            *(uint4*)(tile + BH + so) = *(const uint4*)(Bh + boff + q * 8);
            *(uint4*)(tile + BL + so) = *(const uint4*)(Bl + boff + q * 8);
        }
        __syncthreads();
        compute_chunk<4, 4>(tb + AH, tb + AL, tb + BH, tb + BL, warpM, warpN, lane, acc);
        __syncthreads();
    }

    const int r0 = lane >> 2, cj = (lane & 3) * 2;
#pragma unroll
    for (int mt = 0; mt < 4; mt++) {
#pragma unroll
        for (int nt = 0; nt < 4; nt++) {
            const int m = m0 + warpM + mt * 16 + r0;
            const int n = n0 + warpN + nt * 8 + cj;
            const float* cc = acc[mt][nt];
            if (mode == 2) {
                float b0 = __ldg(bias + n), b1 = __ldg(bias + n + 1);
                *(float2*)(Cf + (size_t)m * N + n)       = make_float2(cc[0] + b0, cc[1] + b1);
                *(float2*)(Cf + (size_t)(m + 8) * N + n) = make_float2(cc[2] + b0, cc[3] + b1);
            } else if (mode == 0) {
                float b0 = __ldg(bias + n), b1 = __ldg(bias + n + 1);
                float v0 = cc[0] + b0, v1 = cc[1] + b1, v2 = cc[2] + b0, v3 = cc[3] + b1;
                __nv_bfloat16 h0 = __float2bfloat16(v0), h1 = __float2bfloat16(v1);
                __nv_bfloat16 h2 = __float2bfloat16(v2), h3 = __float2bfloat16(v3);
                *(uint32_t*)(Ch + (size_t)m * N + n)       = bf2u(h0, h1);
                *(uint32_t*)(Ch + (size_t)(m + 8) * N + n) = bf2u(h2, h3);
                *(uint32_t*)(Cl + (size_t)m * N + n) =
                    packf_hi(v0 - __bfloat162float(h0), v1 - __bfloat162float(h1));
                *(uint32_t*)(Cl + (size_t)(m + 8) * N + n) =
                    packf_hi(v2 - __bfloat162float(h2), v3 - __bfloat162float(h3));
            } else {
                float b0 = __ldg(bias + n), b1 = __ldg(bias + n + 1);
                float v[4] = {cc[0] + b0, cc[1] + b1, cc[2] + b0, cc[3] + b1};
                int mm[4] = {m, m, m + 8, m + 8};
                int nn[4] = {n, n + 1, n, n + 1};
#pragma unroll
                for (int e = 0; e < 4; e++) {
                    __nv_bfloat16 hh = __float2bfloat16(v[e]);
                    Ch[(size_t)nn[e] * vt_stride + mm[e]] = hh;
                    Cl[(size_t)nn[e] * vt_stride + mm[e]] =
                        __float2bfloat16(v[e] - __bfloat162float(hh));
                }
            }
        }
    }
}

// ---------------------------------------------------------------------------
// Scores: attn[h][m][n] = 0.125 * sum_d Q[m][h*64+d]*K[n][h*64+d]  (K depth 64)
// grid (S/128, L/128, H)
// ---------------------------------------------------------------------------
__global__ __launch_bounds__(256)
void scores_hmma(const __nv_bfloat16* __restrict__ Qh, const __nv_bfloat16* __restrict__ Ql,
                 const __nv_bfloat16* __restrict__ Kh, const __nv_bfloat16* __restrict__ Kl,
                 float* __restrict__ attn, int L, int S)
{
    extern __shared__ char smem[];
    const uint32_t sb = smem_u32(smem);
    const uint32_t tb = (sb + 1023) & ~1023u;
    char* tile = smem + (tb - sb);
    const uint32_t AH = 0, AL = 16384, BH = 32768, BL = 49152;

    const int tid = threadIdx.x, wid = tid >> 5, lane = tid & 31;
    const int n0 = blockIdx.x * 128, m0 = blockIdx.y * 128, h = blockIdx.z;
    const int warpM = (wid >> 2) * 64, warpN = (wid & 3) * 32;

    const int lrow = tid >> 1, qb = (tid & 1) * 4;
    const size_t qoff = (size_t)(m0 + lrow) * E_DIM + h * D_HEAD;
    const size_t koff = (size_t)(n0 + lrow) * E_DIM + h * D_HEAD;
#pragma unroll
    for (int j = 0; j < 4; j++) {
        const int q = qb + j;
        const uint32_t so = sw128((uint32_t)lrow * 128 + q * 16);
        *(uint4*)(tile + AH + so) = *(const uint4*)(Qh + qoff + q * 8);
        *(uint4*)(tile + AL + so) = *(const uint4*)(Ql + qoff + q * 8);
        *(uint4*)(tile + BH + so) = *(const uint4*)(Kh + koff + q * 8);
        *(uint4*)(tile + BL + so) = *(const uint4*)(Kl + koff + q * 8);
    }
    __syncthreads();

    float acc[4][4][4];
#pragma unroll
    for (int a = 0; a < 4; a++)
#pragma unroll
        for (int b = 0; b < 4; b++)
#pragma unroll
            for (int c = 0; c < 4; c++) acc[a][b][c] = 0.f;

    compute_chunk<4, 4>(tb + AH, tb + AL, tb + BH, tb + BL, warpM, warpN, lane, acc);

    const int r0 = lane >> 2, cj = (lane & 3) * 2;
#pragma unroll
    for (int mt = 0; mt < 4; mt++) {
#pragma unroll
        for (int nt = 0; nt < 4; nt++) {
            const int m = m0 + warpM + mt * 16 + r0;
            const int n = n0 + warpN + nt * 8 + cj;
            const float* cc = acc[mt][nt];
            *(float2*)(attn + ((size_t)h * L + m) * S + n) =
                make_float2(cc[0] * 0.125f, cc[1] * 0.125f);
            *(float2*)(attn + ((size_t)h * L + m + 8) * S + n) =
                make_float2(cc[2] * 0.125f, cc[3] * 0.125f);
        }
    }
}

// ---------------------------------------------------------------------------
// PV: O[m][h*64+d] = sum_s P[h][m][s]*V[s][h*64+d]. P fp32 -> hi/lo in smem,
// Vt hi/lo pre-transposed [E][S]. Block tile 128x64, warp tile 32x32.
// grid (L/128, H). Writes O hi/lo bf16.
// ---------------------------------------------------------------------------
__global__ __launch_bounds__(256)
void pv_hmma(const float* __restrict__ attn,
             const __nv_bfloat16* __restrict__ Vth, const __nv_bfloat16* __restrict__ Vtl,
             __nv_bfloat16* __restrict__ Oh, __nv_bfloat16* __restrict__ Ol,
             int L, int S)
{
    extern __shared__ char smem[];
    const uint32_t sb = smem_u32(smem);
    const uint32_t tb = (sb + 1023) & ~1023u;
    char* tile = smem + (tb - sb);
    const uint32_t PH = 0, PL = 16384, VH = 32768, VL = 40960;

    const int tid = threadIdx.x, wid = tid >> 5, lane = tid & 31;
    const int m0 = blockIdx.x * 128, h = blockIdx.y;
    const int warpM = (wid >> 1) * 32, warpN = (wid & 1) * 32;

    float acc[2][4][4];
#pragma unroll
    for (int a = 0; a < 2; a++)
#pragma unroll
        for (int b = 0; b < 4; b++)
#pragma unroll
            for (int c = 0; c < 4; c++) acc[a][b][c] = 0.f;

    const int prow = tid >> 1, phalf = tid & 1;
    const int vrow = tid >> 2, vq = tid & 3;

    for (int c = 0; c < (S >> 6); c++) {
        // P fp32 -> hi/lo bf16
        const float4* psrc =
            (const float4*)(attn + ((size_t)h * L + m0 + prow) * S + c * 64 + phalf * 32);
#pragma unroll
        for (int j = 0; j < 8; j++) {
            float4 v = psrc[j];
            __nv_bfloat16 hx = __float2bfloat16(v.x), hy = __float2bfloat16(v.y);
            __nv_bfloat16 hz = __float2bfloat16(v.z), hw = __float2bfloat16(v.w);
            const uint32_t so = sw128((uint32_t)prow * 128 + phalf * 64 + j * 8);
            *(uint2*)(tile + PH + so) = make_uint2(bf2u(hx, hy), bf2u(hz, hw));
            *(uint2*)(tile + PL + so) = make_uint2(
                packf_hi(v.x - __bfloat162float(hx), v.y - __bfloat162float(hy)),
                packf_hi(v.z - __bfloat162float(hz), v.w - __bfloat162float(hw)));
        }
        // Vt tiles (64 rows of 64 bf16)
        const size_t vo = (size_t)(h * 64 + vrow) * S + c * 64;
#pragma unroll
        for (int jj = 0; jj < 2; jj++) {
            const int q = vq + jj * 4;
            const uint32_t so = sw128((uint32_t)vrow * 128 + q * 16);
            *(uint4*)(tile + VH + so) = *(const uint4*)(Vth + vo + q * 8);
            *(uint4*)(tile + VL + so) = *(const uint4*)(Vtl + vo + q * 8);
        }
        __syncthreads();
        compute_chunk<2, 4>(tb + PH, tb + PL, tb + VH, tb + VL, warpM, warpN, lane, acc);
        __syncthreads();
    }

    const int r0 = lane >> 2, cj = (lane & 3) * 2;
#pragma unroll
    for (int mt = 0; mt < 2; mt++) {
#pragma unroll
        for (int nt = 0; nt < 4; nt++) {
            const int m = m0 + warpM + mt * 16 + r0;
            const int n = h * 64 + warpN + nt * 8 + cj;
            const float* cc = acc[mt][nt];
            __nv_bfloat16 h0 = __float2bfloat16(cc[0]), h1 = __float2bfloat16(cc[1]);
            __nv_bfloat16 h2 = __float2bfloat16(cc[2]), h3 = __float2bfloat16(cc[3]);
            *(uint32_t*)(Oh + (size_t)m * E_DIM + n)       = bf2u(h0, h1);
            *(uint32_t*)(Oh + (size_t)(m + 8) * E_DIM + n) = bf2u(h2, h3);
            *(uint32_t*)(Ol + (size_t)m * E_DIM + n) =
                packf_hi(cc[0] - __bfloat162float(h0), cc[1] - __bfloat162float(h1));
            *(uint32_t*)(Ol + (size_t)(m + 8) * E_DIM + n) =
                packf_hi(cc[2] - __bfloat162float(h2), cc[3] - __bfloat162float(h3));
        }
    }
}

// ---------------------------------------------------------------------------
// Row softmax, in-place, optional causal (flag read on device)
// ---------------------------------------------------------------------------
__global__ __launch_bounds__(256)
void softmax_kernel(float* __restrict__ attn, int L, int S,
                    const int* __restrict__ causal_flag)
{
    const int rowi = blockIdx.x;
    const int l = rowi % L;
    const bool causal = (*causal_flag) != 0;
    float* p = attn + (size_t)rowi * S;

    const int tid = threadIdx.x;
    const int per = S / (256 * 4);

    float v[16];
    float m = -INFINITY;
    for (int i = 0; i < per; i++) {
        const int idx4 = tid + i * 256;
        float4 x = *(const float4*)(p + idx4 * 4);
        const int s0 = idx4 * 4;
        float* vv = v + i * 4;
        vv[0] = x.x; vv[1] = x.y; vv[2] = x.z; vv[3] = x.w;
#pragma unroll
        for (int j = 0; j < 4; j++) {
            const bool ok = !causal || (s0 + j <= l);
            if (ok) m = fmaxf(m, vv[j]);
            else vv[j] = -INFINITY;
        }
    }

    __shared__ float red[32];
#pragma unroll
    for (int o = 16; o > 0; o >>= 1) m = fmaxf(m, __shfl_xor_sync(0xffffffffu, m, o));
    if ((tid & 31) == 0) red[tid >> 5] = m;
    __syncthreads();
    if (tid < 32) {
        float t = (tid < 8) ? red[tid] : -INFINITY;
#pragma unroll
        for (int o = 4; o > 0; o >>= 1) t = fmaxf(t, __shfl_xor_sync(0xffffffffu, t, o));
        red[tid] = t;
    }
    __syncthreads();
    m = red[0];

    float sum = 0.f;
    for (int i = 0; i < per * 4; i++) {
        float e = (v[i] == -INFINITY) ? 0.f : __expf(v[i] - m);
        v[i] = e;
        sum += e;
    }
    __syncthreads();
#pragma unroll
    for (int o = 16; o > 0; o >>= 1) sum += __shfl_xor_sync(0xffffffffu, sum, o);
    if ((tid & 31) == 0) red[tid >> 5] = sum;
    __syncthreads();
    if (tid < 32) {
        float t = (tid < 8) ? red[tid] : 0.f;
#pragma unroll
        for (int o = 4; o > 0; o >>= 1) t += __shfl_xor_sync(0xffffffffu, t, o);
        red[tid] = t;
    }
    __syncthreads();
    const float inv = 1.0f / red[0];

    for (int i = 0; i < per; i++) {
        const int idx4 = tid + i * 256;
        float* vv = v + i * 4;
        *(float4*)(p + idx4 * 4) = make_float4(vv[0] * inv, vv[1] * inv, vv[2] * inv, vv[3] * inv);
    }
}

// ---------------------------------------------------------------------------
// Launch
// ---------------------------------------------------------------------------
extern "C" void kernel_launch(void* const* d_in, const int* in_sizes, int n_in,
                              void* d_out, int out_size)
{
    const float* query = (const float*)d_in[0];
    const float* key   = (const float*)d_in[1];
    const float* value = (const float*)d_in[2];
    const float* wq_w  = (const float*)d_in[3];
    const float* wq_b  = (const float*)d_in[4];
    const float* wk_w  = (const float*)d_in[5];
    const float* wk_b  = (const float*)d_in[6];
    const float* wv_w  = (const float*)d_in[7];
    const float* wv_b  = (const float*)d_in[8];
    const float* fc_w  = (const float*)d_in[9];
    const float* fc_b  = (const float*)d_in[10];
    const int* causal  = (const int*)d_in[11];

    const int L = in_sizes[0] / E_DIM;
    const int S = in_sizes[1] / E_DIM;

    float* out = (float*)d_out;
    float* attn_ptr;
    {
        size_t need = (size_t)L * E_DIM + (size_t)H_HEADS * L * S;
        if ((size_t)out_size >= need) attn_ptr = out + (size_t)L * E_DIM;
        else cudaGetSymbolAddress((void**)&attn_ptr, g_attn_fb);
    }

    __nv_bfloat16 *xqh, *xql, *xkh, *xkl, *xvh, *xvl;
    __nv_bfloat16 *wqh, *wql, *wkh, *wkl, *wvh, *wvl, *fch, *fcl;
    __nv_bfloat16 *qh, *ql, *kh, *kl, *vth, *vtl, *oh, *ol;
    cudaGetSymbolAddress((void**)&xqh, g_xq_h); cudaGetSymbolAddress((void**)&xql, g_xq_l);
    cudaGetSymbolAddress((void**)&xkh, g_xk_h); cudaGetSymbolAddress((void**)&xkl, g_xk_l);
    cudaGetSymbolAddress((void**)&xvh, g_xv_h); cudaGetSymbolAddress((void**)&xvl, g_xv_l);
    cudaGetSymbolAddress((void**)&wqh, g_wq_h); cudaGetSymbolAddress((void**)&wql, g_wq_l);
    cudaGetSymbolAddress((void**)&wkh, g_wk_h); cudaGetSymbolAddress((void**)&wkl, g_wk_l);
    cudaGetSymbolAddress((void**)&wvh, g_wv_h); cudaGetSymbolAddress((void**)&wvl, g_wv_l);
    cudaGetSymbolAddress((void**)&fch, g_fc_h); cudaGetSymbolAddress((void**)&fcl, g_fc_l);
    cudaGetSymbolAddress((void**)&qh, g_q_h);   cudaGetSymbolAddress((void**)&ql, g_q_l);
    cudaGetSymbolAddress((void**)&kh, g_k_h);   cudaGetSymbolAddress((void**)&kl, g_k_l);
    cudaGetSymbolAddress((void**)&vth, g_vt_h); cudaGetSymbolAddress((void**)&vtl, g_vt_l);
    cudaGetSymbolAddress((void**)&oh, g_o_h);   cudaGetSymbolAddress((void**)&ol, g_o_l);

    const int GEMM_SMEM   = 1024 + 65536;
    const int SCORES_SMEM = 1024 + 65536;
    const int PV_SMEM     = 1024 + 49152;
    cudaFuncSetAttribute(gemm_hmma,   cudaFuncAttributeMaxDynamicSharedMemorySize, GEMM_SMEM);
    cudaFuncSetAttribute(scores_hmma, cudaFuncAttributeMaxDynamicSharedMemorySize, SCORES_SMEM);
    cudaFuncSetAttribute(pv_hmma,     cudaFuncAttributeMaxDynamicSharedMemorySize, PV_SMEM);

    // 1) hi/lo conversions
    {
        const int nx4 = (L * E_DIM) / 4, nw4 = (E_DIM * E_DIM) / 4;
        cvt_hilo<<<512, 256>>>(query, xqh, xql, nx4);
        cvt_hilo<<<512, 256>>>(key,   xkh, xkl, nx4);
        cvt_hilo<<<512, 256>>>(value, xvh, xvl, nx4);
        cvt_hilo<<<256, 256>>>(wq_w,  wqh, wql, nw4);
        cvt_hilo<<<256, 256>>>(wk_w,  wkh, wkl, nw4);
        cvt_hilo<<<256, 256>>>(wv_w,  wvh, wvl, nw4);
        cvt_hilo<<<256, 256>>>(fc_w,  fch, fcl, nw4);
    }

    // 2) projections
    {
        dim3 grid(E_DIM / 128, L / 128);
        gemm_hmma<<<grid, 256, GEMM_SMEM>>>(xqh, xql, wqh, wql, wq_b, qh, ql, nullptr, 0, E_DIM, E_DIM, 0);
        gemm_hmma<<<grid, 256, GEMM_SMEM>>>(xkh, xkl, wkh, wkl, wk_b, kh, kl, nullptr, 0, E_DIM, E_DIM, 0);
        gemm_hmma<<<grid, 256, GEMM_SMEM>>>(xvh, xvl, wvh, wvl, wv_b, vth, vtl, nullptr, 1, E_DIM, E_DIM, S);
    }

    // 3) scores
    {
        dim3 grid(S / 128, L / 128, H_HEADS);
        scores_hmma<<<grid, 256, SCORES_SMEM>>>(qh, ql, kh, kl, attn_ptr, L, S);
    }

    // 4) softmax
    softmax_kernel<<<H_HEADS * L, 256>>>(attn_ptr, L, S, causal);

    // 5) PV
    {
        dim3 grid(L / 128, H_HEADS);
        pv_hmma<<<grid, 256, PV_SMEM>>>(attn_ptr, vth, vtl, oh, ol, L, S);
    }

    // 6) FC
    {
        dim3 grid(E_DIM / 128, L / 128);
        gemm_hmma<<<grid, 256, GEMM_SMEM>>>(oh, ol, fch, fcl, fc_b, nullptr, nullptr, out, 2, E_DIM, E_DIM, 0);
    }
}